// round 8
// baseline (speedup 1.0000x reference)
#include <cuda_runtime.h>
#include <cuda_fp16.h>
#include <cstdint>

#define MAXN 50000
#define MAXE 1600000
#define F_IN 512
#define C1 64      // heads*hid = 8*8
#define HEADS 8
#define CLS 16
#define SCAN_B 256

// packed fp32x2 FMA (sm_103a)
#define FMA_F32X2(d, a, b, c) \
    asm("fma.rn.f32x2 %0, %1, %2, %3;" : "=l"(d) : "l"(a), "l"(b), "l"(c))
#define PACK_DUP_F32X2(d, f) \
    asm("mov.b64 %0, {%1, %1};" : "=l"(d) : "r"(__float_as_uint(f)))

// ---------------- scratch ----------------
__device__ __align__(16) int    g_deg[MAXN];       // zeroed via cudaMemsetAsync
__device__ __align__(16) int    g_tmp[MAXN];       // zeroed via cudaMemsetAsync
__device__ __align__(16) int    g_rowptr[MAXN + 1];
__device__ __align__(16) int    g_bsum[256];
__device__ __align__(16) int    g_boff[256];
__device__ __align__(16) int    g_col[MAXE + MAXN];
__device__ __align__(16) __half g_h1h[(size_t)MAXN * C1];   // fp16 features for gather
__device__ __align__(16) float  g_asrc1[MAXN * HEADS];
__device__ __align__(16) float  g_adst1[MAXN * HEADS];
__device__ __align__(16) float  g_h1act[(size_t)MAXN * C1];
__device__ __align__(16) float  g_h2[(size_t)MAXN * CLS];
__device__ __align__(16) float  g_asrc2[MAXN];
__device__ __align__(16) float  g_adst2[MAXN];

// Per-block int64-vs-int32 probe: deterministic for fixed input.
__device__ __forceinline__ bool block_detect_is64(const int* w32, long long e0, int E) {
    int hi = 0;
    long long e = e0 + threadIdx.x;
    if (e < E) hi = w32[2 * e + 1];
    return !__syncthreads_or(hi != 0);
}

__device__ __forceinline__ int load_edge(const void* ei, bool is64, size_t pos) {
    return is64 ? (int)((const long long*)ei)[pos] : ((const int*)ei)[pos];
}

// ================= degree count (standalone, runs first) =================
__global__ void k_count(const void* __restrict__ ei, int E, int n) {
    long long e0 = (long long)blockIdx.x * 256;
    bool is64 = block_detect_is64((const int*)ei, e0, E);
    long long e = e0 + threadIdx.x;
    if (e < E) {
        int d = load_edge(ei, is64, (size_t)E + e);
        if ((unsigned)d < (unsigned)n) atomicAdd(&g_deg[d], 1);
    }
}

// ================= fused GEMM1 (f32x2) + CSR scatter =================
// blocks [0, GB): gemm1;  blocks [GB, ...): scatter (needs rowptr from scans)
#define TK 32
__global__ __launch_bounds__(256) void k_gemm1_scatter(
    const float* __restrict__ x, const float* __restrict__ W,
    const float* __restrict__ attS, const float* __restrict__ attD,
    const void* __restrict__ ei, int n, int E, int GB)
{
    if (blockIdx.x >= GB) {
        long long e0 = (long long)(blockIdx.x - GB) * 256;
        bool is64 = block_detect_is64((const int*)ei, e0, E);
        long long i = e0 + threadIdx.x;
        int s, d;
        if (i < E) {
            d = load_edge(ei, is64, (size_t)E + i);
            if ((unsigned)d >= (unsigned)n) return;       // must match k_count guard
            s = load_edge(ei, is64, (size_t)i);
            if ((unsigned)s >= (unsigned)n) s = 0;
        } else if (i < E + n) {
            s = d = (int)(i - E);
        } else return;
        int pos = g_rowptr[d] + atomicAdd(&g_tmp[d], 1);
        g_col[pos] = s;
        return;
    }

    __shared__ __align__(16) float xs[TK][256 + 4];
    __shared__ __align__(16) float ws[TK][64 + 4];
    int tid = threadIdx.x;
    int tx = tid & 7;       // col group (== head)
    int ty = tid >> 3;      // row group 0..31
    int r0 = blockIdx.x * 256;

    unsigned long long acc2[8][4];
#pragma unroll
    for (int r = 0; r < 8; r++)
#pragma unroll
        for (int c = 0; c < 4; c++) acc2[r][c] = 0ull;

    for (int kc = 0; kc < F_IN; kc += TK) {
#pragma unroll
        for (int i = 0; i < 8; i++) {
            int idx = tid + 256 * i;
            int row = idx >> 3;
            int k4  = idx & 7;
            float4 v = make_float4(0.f, 0.f, 0.f, 0.f);
            int gr = r0 + row;
            if (gr < n) v = *(const float4*)&x[(size_t)gr * F_IN + kc + k4 * 4];
            xs[k4 * 4 + 0][row] = v.x;
            xs[k4 * 4 + 1][row] = v.y;
            xs[k4 * 4 + 2][row] = v.z;
            xs[k4 * 4 + 3][row] = v.w;
        }
#pragma unroll
        for (int i = 0; i < 2; i++) {
            int idx = tid + 256 * i;
            int k  = idx >> 4;
            int c4 = idx & 15;
            float4 v = *(const float4*)&W[(size_t)(kc + k) * C1 + c4 * 4];
            ws[k][c4 * 4 + 0] = v.x;
            ws[k][c4 * 4 + 1] = v.y;
            ws[k][c4 * 4 + 2] = v.z;
            ws[k][c4 * 4 + 3] = v.w;
        }
        __syncthreads();
#pragma unroll
        for (int k = 0; k < TK; k++) {
            float4 xa = *(const float4*)&xs[k][ty * 8];
            float4 xb = *(const float4*)&xs[k][ty * 8 + 4];
            unsigned long long wv2[4];
            {
                const ulonglong2* wp = (const ulonglong2*)&ws[k][tx * 8];
                ulonglong2 w01 = wp[0];
                ulonglong2 w23 = wp[1];
                wv2[0] = w01.x; wv2[1] = w01.y;
                wv2[2] = w23.x; wv2[3] = w23.y;
            }
            unsigned long long xp[8];
            PACK_DUP_F32X2(xp[0], xa.x); PACK_DUP_F32X2(xp[1], xa.y);
            PACK_DUP_F32X2(xp[2], xa.z); PACK_DUP_F32X2(xp[3], xa.w);
            PACK_DUP_F32X2(xp[4], xb.x); PACK_DUP_F32X2(xp[5], xb.y);
            PACK_DUP_F32X2(xp[6], xb.z); PACK_DUP_F32X2(xp[7], xb.w);
#pragma unroll
            for (int r = 0; r < 8; r++)
#pragma unroll
                for (int c = 0; c < 4; c++)
                    FMA_F32X2(acc2[r][c], xp[r], wv2[c], acc2[r][c]);
        }
        __syncthreads();
    }

    float as[8], ad[8];
#pragma unroll
    for (int c = 0; c < 8; c++) { as[c] = attS[tx * 8 + c]; ad[c] = attD[tx * 8 + c]; }
#pragma unroll
    for (int r = 0; r < 8; r++) {
        int gr = r0 + ty * 8 + r;
        if (gr < n) {
            float a[8];
#pragma unroll
            for (int c = 0; c < 4; c++) {
                uint2 u = *(uint2*)&acc2[r][c];
                a[2 * c]     = __uint_as_float(u.x);
                a[2 * c + 1] = __uint_as_float(u.y);
            }
            float s = 0.f, d = 0.f;
#pragma unroll
            for (int c = 0; c < 8; c++) {
                s = fmaf(a[c], as[c], s);         // logits from fp32 accs
                d = fmaf(a[c], ad[c], d);
            }
            // store features as fp16 (halves agg1 gather traffic)
            __half2 hh[4];
#pragma unroll
            for (int c = 0; c < 4; c++)
                hh[c] = __floats2half2_rn(a[2 * c], a[2 * c + 1]);
            uint4 pv;
            pv.x = *(unsigned*)&hh[0]; pv.y = *(unsigned*)&hh[1];
            pv.z = *(unsigned*)&hh[2]; pv.w = *(unsigned*)&hh[3];
            *(uint4*)&g_h1h[(size_t)gr * C1 + tx * 8] = pv;
            g_asrc1[gr * HEADS + tx] = s;
            g_adst1[gr * HEADS + tx] = d;
        }
    }
}

// ================= 3-stage block scan of (deg + 1 self-loop) =================
__device__ __forceinline__ int warp_incl_scan(int x) {
#pragma unroll
    for (int o = 1; o < 32; o <<= 1) {
        int t = __shfl_up_sync(0xffffffffu, x, o);
        if ((threadIdx.x & 31) >= o) x += t;
    }
    return x;
}

__global__ void k_scan1(int n) {
    __shared__ int wsum[8];
    int i = blockIdx.x * SCAN_B + threadIdx.x;
    int lane = threadIdx.x & 31, wid = threadIdx.x >> 5;
    int v = (i < n) ? g_deg[i] + 1 : 0;     // +1 = self-loop
    int x = warp_incl_scan(v);
    if (lane == 31) wsum[wid] = x;
    __syncthreads();
    if (wid == 0) {
        int y = (lane < 8) ? wsum[lane] : 0;
#pragma unroll
        for (int o = 1; o < 8; o <<= 1) {
            int t = __shfl_up_sync(0xffffffffu, y, o);
            if (lane >= o) y += t;
        }
        if (lane < 8) wsum[lane] = y;
    }
    __syncthreads();
    int excl = x - v + (wid > 0 ? wsum[wid - 1] : 0);
    if (i < n) g_rowptr[i] = excl;
    if (threadIdx.x == 0) g_bsum[blockIdx.x] = wsum[7];
}

__global__ void k_scan2(int nb, int n) {    // nb <= 256
    __shared__ int wsum[8];
    int t = threadIdx.x;
    int lane = t & 31, wid = t >> 5;
    int v = (t < nb) ? g_bsum[t] : 0;
    int x = warp_incl_scan(v);
    if (lane == 31) wsum[wid] = x;
    __syncthreads();
    if (wid == 0) {
        int y = (lane < 8) ? wsum[lane] : 0;
#pragma unroll
        for (int o = 1; o < 8; o <<= 1) {
            int tt = __shfl_up_sync(0xffffffffu, y, o);
            if (lane >= o) y += tt;
        }
        if (lane < 8) wsum[lane] = y;
    }
    __syncthreads();
    int excl = x - v + (wid > 0 ? wsum[wid - 1] : 0);
    if (t < nb) g_boff[t] = excl;
    if (t == 0) g_rowptr[n] = wsum[7];
}

__global__ void k_scan3(int n) {
    int i = blockIdx.x * SCAN_B + threadIdx.x;
    if (i < n) g_rowptr[i] += g_boff[blockIdx.x];
}

// ================= layer-1 edge softmax + aggregate + bias + elu =================
// one warp per dst node; lane owns channels 2l, 2l+1 (head hown = l>>2).
// 4-way unrolled; fp16 feature gathers, fp32 math.
__global__ __launch_bounds__(256) void agg1(const float* __restrict__ bias1, int n) {
    int warp = (blockIdx.x * blockDim.x + threadIdx.x) >> 5;
    int lane = threadIdx.x & 31;
    if (warp >= n) return;
    int nd = warp;
    int h    = lane & 7;
    int hown = lane >> 2;
    float laneden = (lane < 8) ? 1.f : 0.f;

    float adv = g_adst1[nd * HEADS + h];
    int beg = g_rowptr[nd], end = g_rowptr[nd + 1];
    float accx = 0.f, accy = 0.f, den = 0.f;

    int e = beg;
    for (; e + 4 <= end; e += 4) {
        int s0 = g_col[e];
        int s1 = g_col[e + 1];
        int s2 = g_col[e + 2];
        int s3 = g_col[e + 3];
        float a0 = g_asrc1[s0 * HEADS + h] + adv;
        float a1 = g_asrc1[s1 * HEADS + h] + adv;
        float a2 = g_asrc1[s2 * HEADS + h] + adv;
        float a3 = g_asrc1[s3 * HEADS + h] + adv;
        __half2 q0 = *(const __half2*)&g_h1h[(size_t)s0 * C1 + 2 * lane];
        __half2 q1 = *(const __half2*)&g_h1h[(size_t)s1 * C1 + 2 * lane];
        __half2 q2 = *(const __half2*)&g_h1h[(size_t)s2 * C1 + 2 * lane];
        __half2 q3 = *(const __half2*)&g_h1h[(size_t)s3 * C1 + 2 * lane];
        a0 = a0 > 0.f ? a0 : 0.2f * a0;
        a1 = a1 > 0.f ? a1 : 0.2f * a1;
        a2 = a2 > 0.f ? a2 : 0.2f * a2;
        a3 = a3 > 0.f ? a3 : 0.2f * a3;
        float w0 = __expf(a0);
        float w1 = __expf(a1);
        float w2 = __expf(a2);
        float w3 = __expf(a3);
        den = fmaf((w0 + w1) + (w2 + w3), laneden, den);
        float w0o = __shfl_sync(0xffffffffu, w0, hown);
        float w1o = __shfl_sync(0xffffffffu, w1, hown);
        float w2o = __shfl_sync(0xffffffffu, w2, hown);
        float w3o = __shfl_sync(0xffffffffu, w3, hown);
        float2 f0 = __half22float2(q0);
        float2 f1 = __half22float2(q1);
        float2 f2 = __half22float2(q2);
        float2 f3 = __half22float2(q3);
        accx = fmaf(w0o, f0.x, accx);
        accy = fmaf(w0o, f0.y, accy);
        accx = fmaf(w1o, f1.x, accx);
        accy = fmaf(w1o, f1.y, accy);
        accx = fmaf(w2o, f2.x, accx);
        accy = fmaf(w2o, f2.y, accy);
        accx = fmaf(w3o, f3.x, accx);
        accy = fmaf(w3o, f3.y, accy);
    }
    for (; e < end; e++) {
        int s0 = g_col[e];
        float a0 = g_asrc1[s0 * HEADS + h] + adv;
        __half2 q0 = *(const __half2*)&g_h1h[(size_t)s0 * C1 + 2 * lane];
        a0 = a0 > 0.f ? a0 : 0.2f * a0;
        float w0 = __expf(a0);
        den = fmaf(w0, laneden, den);
        float w0o = __shfl_sync(0xffffffffu, w0, hown);
        float2 f0 = __half22float2(q0);
        accx = fmaf(w0o, f0.x, accx);
        accy = fmaf(w0o, f0.y, accy);
    }
    float deno = __shfl_sync(0xffffffffu, den, hown);
    float2 bv = *(const float2*)&bias1[2 * lane];
    float ox = accx / deno + bv.x;
    float oy = accy / deno + bv.y;
    ox = ox > 0.f ? ox : expm1f(ox);          // elu
    oy = oy > 0.f ? oy : expm1f(oy);
    *(float2*)&g_h1act[(size_t)nd * C1 + 2 * lane] = make_float2(ox, oy);
}

// ================= GEMM2: h2 = h1act @ W2, fused scalar logits =================
__global__ __launch_bounds__(256) void gemm2(
    const float* __restrict__ W2, const float* __restrict__ aS,
    const float* __restrict__ aD, int n)
{
    __shared__ float ws[64 * 16];
    int tid = threadIdx.x;
    for (int i = tid; i < 64 * 16; i += 256) ws[i] = W2[i];
    __syncthreads();

    int warp = tid >> 5, lane = tid & 31;
    int row0 = (blockIdx.x * 8 + warp) * 2 + (lane >> 4);
    int c = lane & 15;
    bool ok = row0 < n;
    int row = ok ? row0 : 0;

    float xr[4];
#pragma unroll
    for (int j = 0; j < 4; j++) xr[j] = g_h1act[(size_t)row * C1 + c + 16 * j];

    float acc = 0.f;
#pragma unroll
    for (int k = 0; k < 64; k++) {
        float xk = __shfl_sync(0xffffffffu, xr[k >> 4], (lane & 16) | (k & 15));
        acc = fmaf(xk, ws[k * 16 + c], acc);
    }

    float ts = acc * aS[c];
    float td = acc * aD[c];
#pragma unroll
    for (int off = 8; off >= 1; off >>= 1) {
        ts += __shfl_xor_sync(0xffffffffu, ts, off);
        td += __shfl_xor_sync(0xffffffffu, td, off);
    }
    if (ok) {
        g_h2[(size_t)row * CLS + c] = acc;
        if (c == 0) { g_asrc2[row] = ts; g_adst2[row] = td; }
    }
}

// ================= layer-2 aggregate + bias + log_softmax =================
__global__ __launch_bounds__(256) void agg2(
    const float* __restrict__ bias2, float* __restrict__ out, int n)
{
    int warp = (blockIdx.x * blockDim.x + threadIdx.x) >> 5;
    int lane = threadIdx.x & 31;
    int node0 = warp * 2 + (lane >> 4);
    int c = lane & 15;
    bool ok = node0 < n;
    int nd = ok ? node0 : 0;

    float adv = g_adst2[nd];
    int beg = g_rowptr[nd];
    int end = ok ? g_rowptr[nd + 1] : beg;
    float acc = 0.f, den = 0.f;
    int e = beg;
    for (; e + 2 <= end; e += 2) {
        int s0 = g_col[e], s1 = g_col[e + 1];
        float a0 = g_asrc2[s0] + adv;
        float a1 = g_asrc2[s1] + adv;
        float f0 = g_h2[(size_t)s0 * CLS + c];
        float f1 = g_h2[(size_t)s1 * CLS + c];
        a0 = a0 > 0.f ? a0 : 0.2f * a0;
        a1 = a1 > 0.f ? a1 : 0.2f * a1;
        float w0 = __expf(a0), w1 = __expf(a1);
        den += w0 + w1;
        acc = fmaf(w0, f0, acc);
        acc = fmaf(w1, f1, acc);
    }
    if (e < end) {
        int s0 = g_col[e];
        float a0 = g_asrc2[s0] + adv;
        a0 = a0 > 0.f ? a0 : 0.2f * a0;
        float w0 = __expf(a0);
        den += w0;
        acc = fmaf(w0, g_h2[(size_t)s0 * CLS + c], acc);
    }
    float val = ok ? (acc / den + bias2[c]) : 0.f;
    float m = val;
#pragma unroll
    for (int off = 8; off >= 1; off >>= 1)
        m = fmaxf(m, __shfl_xor_sync(0xffffffffu, m, off));
    float ex = __expf(val - m);
    float s = ex;
#pragma unroll
    for (int off = 8; off >= 1; off >>= 1)
        s += __shfl_xor_sync(0xffffffffu, s, off);
    if (ok) out[(size_t)node0 * CLS + c] = val - m - __logf(s);
}

// ---------------- launch ----------------
extern "C" void kernel_launch(void* const* d_in, const int* in_sizes, int n_in,
                              void* d_out, int out_size) {
    const float* x     = (const float*)d_in[0];
    const void*  ei    = d_in[1];
    const float* W1    = (const float*)d_in[2];
    const float* attS1 = (const float*)d_in[3];
    const float* attD1 = (const float*)d_in[4];
    const float* bias1 = (const float*)d_in[5];
    const float* W2    = (const float*)d_in[6];
    const float* attS2 = (const float*)d_in[7];
    const float* attD2 = (const float*)d_in[8];
    const float* bias2 = (const float*)d_in[9];
    float* out = (float*)d_out;

    int n = in_sizes[0] / F_IN;      // 50000
    int E = in_sizes[1] / 2;         // 1600000

    void *p_deg = nullptr, *p_tmp = nullptr;
    cudaGetSymbolAddress(&p_deg, g_deg);
    cudaGetSymbolAddress(&p_tmp, g_tmp);
    cudaMemsetAsync(p_deg, 0, (size_t)n * sizeof(int));
    cudaMemsetAsync(p_tmp, 0, (size_t)n * sizeof(int));

    int GB = (n + 255) / 256;                 // gemm1 blocks (196)
    int CB = (E + 255) / 256;                 // count blocks (6250)
    int SB = (E + n + 255) / 256;             // scatter blocks (6446)
    int nb = (n + SCAN_B - 1) / SCAN_B;       // scan blocks (196)

    k_count<<<CB, 256>>>(ei, E, n);           // cheap; unblocks scans early
    k_scan1<<<nb, SCAN_B>>>(n);
    k_scan2<<<1, 256>>>(nb, n);
    k_scan3<<<nb, SCAN_B>>>(n);
    k_gemm1_scatter<<<GB + SB, 256>>>(x, W1, attS1, attD1, ei, n, E, GB);  // scatter hides under gemm1

    agg1 <<<(n + 7) / 8, 256>>>(bias1, n);
    gemm2<<<(n + 15) / 16, 256>>>(W2, attS2, attD2, n);
    agg2 <<<(n + 15) / 16, 256>>>(bias2, out, n);
}

// round 9
// speedup vs baseline: 1.0514x; 1.0514x over previous
#include <cuda_runtime.h>
#include <cuda_fp16.h>
#include <cstdint>

#define MAXN 50000
#define MAXE 1600000
#define F_IN 512
#define C1 64      // heads*hid = 8*8
#define HEADS 8
#define CLS 16
#define SCAN_B 256

// packed fp32x2 FMA (sm_103a)
#define FMA_F32X2(d, a, b, c) \
    asm("fma.rn.f32x2 %0, %1, %2, %3;" : "=l"(d) : "l"(a), "l"(b), "l"(c))
#define PACK_DUP_F32X2(d, f) \
    asm("mov.b64 %0, {%1, %1};" : "=l"(d) : "r"(__float_as_uint(f)))

// ---------------- scratch ----------------
__device__ __align__(16) int    g_deg[MAXN];       // zeroed via cudaMemsetAsync
__device__ __align__(16) int    g_tmp[MAXN];       // zeroed via cudaMemsetAsync
__device__ __align__(16) int    g_rowptr[MAXN + 1];
__device__ __align__(16) int    g_bsum[256];
__device__ __align__(16) int    g_boff[256];
__device__ __align__(16) int    g_col[MAXE + MAXN];
__device__ __align__(16) __half g_h1h[(size_t)MAXN * C1];   // fp16 features for gather
__device__ __align__(16) float  g_asrc1[MAXN * HEADS];
__device__ __align__(16) float  g_adst1[MAXN * HEADS];
__device__ __align__(16) float  g_h1act[(size_t)MAXN * C1];
__device__ __align__(16) float  g_h2[(size_t)MAXN * CLS];
__device__ __align__(16) float  g_asrc2[MAXN];
__device__ __align__(16) float  g_adst2[MAXN];

// Per-block int64-vs-int32 probe: deterministic for fixed input.
__device__ __forceinline__ bool block_detect_is64(const int* w32, long long e0, int E) {
    int hi = 0;
    long long e = e0 + threadIdx.x;
    if (e < E) hi = w32[2 * e + 1];
    return !__syncthreads_or(hi != 0);
}

__device__ __forceinline__ int load_edge(const void* ei, bool is64, size_t pos) {
    return is64 ? (int)((const long long*)ei)[pos] : ((const int*)ei)[pos];
}

// ================= fused GEMM1 (f32x2 packed) + edge count =================
// blocks [0, GB): gemm1;  blocks [GB, ...): degree count (hidden under gemm1)
#define TK 32
__global__ __launch_bounds__(256) void k_gemm1_count(
    const float* __restrict__ x, const float* __restrict__ W,
    const float* __restrict__ attS, const float* __restrict__ attD,
    const void* __restrict__ ei, int n, int E, int GB)
{
    if (blockIdx.x >= GB) {
        long long e0 = (long long)(blockIdx.x - GB) * 256;
        bool is64 = block_detect_is64((const int*)ei, e0, E);
        long long e = e0 + threadIdx.x;
        if (e < E) {
            int d = load_edge(ei, is64, (size_t)E + e);
            if ((unsigned)d < (unsigned)n) atomicAdd(&g_deg[d], 1);
        }
        return;
    }

    __shared__ __align__(16) float xs[TK][256 + 4];
    __shared__ __align__(16) float ws[TK][64 + 4];
    int tid = threadIdx.x;
    int tx = tid & 7;       // col group (== head)
    int ty = tid >> 3;      // row group 0..31
    int r0 = blockIdx.x * 256;

    unsigned long long acc2[8][4];
#pragma unroll
    for (int r = 0; r < 8; r++)
#pragma unroll
        for (int c = 0; c < 4; c++) acc2[r][c] = 0ull;

    for (int kc = 0; kc < F_IN; kc += TK) {
#pragma unroll
        for (int i = 0; i < 8; i++) {
            int idx = tid + 256 * i;
            int row = idx >> 3;
            int k4  = idx & 7;
            float4 v = make_float4(0.f, 0.f, 0.f, 0.f);
            int gr = r0 + row;
            if (gr < n) v = *(const float4*)&x[(size_t)gr * F_IN + kc + k4 * 4];
            xs[k4 * 4 + 0][row] = v.x;
            xs[k4 * 4 + 1][row] = v.y;
            xs[k4 * 4 + 2][row] = v.z;
            xs[k4 * 4 + 3][row] = v.w;
        }
#pragma unroll
        for (int i = 0; i < 2; i++) {
            int idx = tid + 256 * i;
            int k  = idx >> 4;
            int c4 = idx & 15;
            float4 v = *(const float4*)&W[(size_t)(kc + k) * C1 + c4 * 4];
            ws[k][c4 * 4 + 0] = v.x;
            ws[k][c4 * 4 + 1] = v.y;
            ws[k][c4 * 4 + 2] = v.z;
            ws[k][c4 * 4 + 3] = v.w;
        }
        __syncthreads();
#pragma unroll
        for (int k = 0; k < TK; k++) {
            float4 xa = *(const float4*)&xs[k][ty * 8];
            float4 xb = *(const float4*)&xs[k][ty * 8 + 4];
            unsigned long long wv2[4];
            {
                const ulonglong2* wp = (const ulonglong2*)&ws[k][tx * 8];
                ulonglong2 w01 = wp[0];
                ulonglong2 w23 = wp[1];
                wv2[0] = w01.x; wv2[1] = w01.y;
                wv2[2] = w23.x; wv2[3] = w23.y;
            }
            unsigned long long xp[8];
            PACK_DUP_F32X2(xp[0], xa.x); PACK_DUP_F32X2(xp[1], xa.y);
            PACK_DUP_F32X2(xp[2], xa.z); PACK_DUP_F32X2(xp[3], xa.w);
            PACK_DUP_F32X2(xp[4], xb.x); PACK_DUP_F32X2(xp[5], xb.y);
            PACK_DUP_F32X2(xp[6], xb.z); PACK_DUP_F32X2(xp[7], xb.w);
#pragma unroll
            for (int r = 0; r < 8; r++)
#pragma unroll
                for (int c = 0; c < 4; c++)
                    FMA_F32X2(acc2[r][c], xp[r], wv2[c], acc2[r][c]);
        }
        __syncthreads();
    }

    float as[8], ad[8];
#pragma unroll
    for (int c = 0; c < 8; c++) { as[c] = attS[tx * 8 + c]; ad[c] = attD[tx * 8 + c]; }
#pragma unroll
    for (int r = 0; r < 8; r++) {
        int gr = r0 + ty * 8 + r;
        if (gr < n) {
            float a[8];
#pragma unroll
            for (int c = 0; c < 4; c++) {
                uint2 u = *(uint2*)&acc2[r][c];
                a[2 * c]     = __uint_as_float(u.x);
                a[2 * c + 1] = __uint_as_float(u.y);
            }
            float s = 0.f, d = 0.f;
#pragma unroll
            for (int c = 0; c < 8; c++) {
                s = fmaf(a[c], as[c], s);         // logits from fp32 accs
                d = fmaf(a[c], ad[c], d);
            }
            // store features as fp16 (halves agg1 gather traffic)
            __half2 hh[4];
#pragma unroll
            for (int c = 0; c < 4; c++)
                hh[c] = __floats2half2_rn(a[2 * c], a[2 * c + 1]);
            uint4 pv;
            pv.x = *(unsigned*)&hh[0]; pv.y = *(unsigned*)&hh[1];
            pv.z = *(unsigned*)&hh[2]; pv.w = *(unsigned*)&hh[3];
            *(uint4*)&g_h1h[(size_t)gr * C1 + tx * 8] = pv;
            g_asrc1[gr * HEADS + tx] = s;
            g_adst1[gr * HEADS + tx] = d;
        }
    }
}

// ================= 3-stage block scan of (deg + 1 self-loop) =================
__device__ __forceinline__ int warp_incl_scan(int x) {
#pragma unroll
    for (int o = 1; o < 32; o <<= 1) {
        int t = __shfl_up_sync(0xffffffffu, x, o);
        if ((threadIdx.x & 31) >= o) x += t;
    }
    return x;
}

__global__ void k_scan1(int n) {
    __shared__ int wsum[8];
    int i = blockIdx.x * SCAN_B + threadIdx.x;
    int lane = threadIdx.x & 31, wid = threadIdx.x >> 5;
    int v = (i < n) ? g_deg[i] + 1 : 0;     // +1 = self-loop
    int x = warp_incl_scan(v);
    if (lane == 31) wsum[wid] = x;
    __syncthreads();
    if (wid == 0) {
        int y = (lane < 8) ? wsum[lane] : 0;
#pragma unroll
        for (int o = 1; o < 8; o <<= 1) {
            int t = __shfl_up_sync(0xffffffffu, y, o);
            if (lane >= o) y += t;
        }
        if (lane < 8) wsum[lane] = y;
    }
    __syncthreads();
    int excl = x - v + (wid > 0 ? wsum[wid - 1] : 0);
    if (i < n) g_rowptr[i] = excl;
    if (threadIdx.x == 0) g_bsum[blockIdx.x] = wsum[7];
}

__global__ void k_scan2(int nb, int n) {    // nb <= 256
    __shared__ int wsum[8];
    int t = threadIdx.x;
    int lane = t & 31, wid = t >> 5;
    int v = (t < nb) ? g_bsum[t] : 0;
    int x = warp_incl_scan(v);
    if (lane == 31) wsum[wid] = x;
    __syncthreads();
    if (wid == 0) {
        int y = (lane < 8) ? wsum[lane] : 0;
#pragma unroll
        for (int o = 1; o < 8; o <<= 1) {
            int tt = __shfl_up_sync(0xffffffffu, y, o);
            if (lane >= o) y += tt;
        }
        if (lane < 8) wsum[lane] = y;
    }
    __syncthreads();
    int excl = x - v + (wid > 0 ? wsum[wid - 1] : 0);
    if (t < nb) g_boff[t] = excl;
    if (t == 0) g_rowptr[n] = wsum[7];
}

__global__ void k_scan3(int n) {
    int i = blockIdx.x * SCAN_B + threadIdx.x;
    if (i < n) g_rowptr[i] += g_boff[blockIdx.x];
}

// ================= scatter (edges then self-loops) =================
__global__ void k_scatter(const void* __restrict__ ei, int E, int n) {
    long long e0 = (long long)blockIdx.x * 256;
    bool is64 = block_detect_is64((const int*)ei, e0, E);
    long long i = e0 + threadIdx.x;
    int s, d;
    if (i < E) {
        d = load_edge(ei, is64, (size_t)E + i);
        if ((unsigned)d >= (unsigned)n) return;       // must match k_count guard
        s = load_edge(ei, is64, (size_t)i);
        if ((unsigned)s >= (unsigned)n) s = 0;
    } else if (i < E + n) {
        s = d = (int)(i - E);
    } else return;
    int pos = g_rowptr[d] + atomicAdd(&g_tmp[d], 1);
    g_col[pos] = s;
}

// ================= layer-1 edge softmax + aggregate + bias + elu =================
// one warp per dst node; lane owns channels 2l, 2l+1 (head hown = l>>2).
// 4-way unrolled; fp16 feature gathers, fp32 math.
__global__ __launch_bounds__(256) void agg1(const float* __restrict__ bias1, int n) {
    int warp = (blockIdx.x * blockDim.x + threadIdx.x) >> 5;
    int lane = threadIdx.x & 31;
    if (warp >= n) return;
    int nd = warp;
    int h    = lane & 7;
    int hown = lane >> 2;
    float laneden = (lane < 8) ? 1.f : 0.f;

    float adv = g_adst1[nd * HEADS + h];
    int beg = g_rowptr[nd], end = g_rowptr[nd + 1];
    float accx = 0.f, accy = 0.f, den = 0.f;

    int e = beg;
    for (; e + 4 <= end; e += 4) {
        int s0 = g_col[e];
        int s1 = g_col[e + 1];
        int s2 = g_col[e + 2];
        int s3 = g_col[e + 3];
        float a0 = g_asrc1[s0 * HEADS + h] + adv;
        float a1 = g_asrc1[s1 * HEADS + h] + adv;
        float a2 = g_asrc1[s2 * HEADS + h] + adv;
        float a3 = g_asrc1[s3 * HEADS + h] + adv;
        __half2 q0 = *(const __half2*)&g_h1h[(size_t)s0 * C1 + 2 * lane];
        __half2 q1 = *(const __half2*)&g_h1h[(size_t)s1 * C1 + 2 * lane];
        __half2 q2 = *(const __half2*)&g_h1h[(size_t)s2 * C1 + 2 * lane];
        __half2 q3 = *(const __half2*)&g_h1h[(size_t)s3 * C1 + 2 * lane];
        a0 = a0 > 0.f ? a0 : 0.2f * a0;
        a1 = a1 > 0.f ? a1 : 0.2f * a1;
        a2 = a2 > 0.f ? a2 : 0.2f * a2;
        a3 = a3 > 0.f ? a3 : 0.2f * a3;
        float w0 = __expf(a0);
        float w1 = __expf(a1);
        float w2 = __expf(a2);
        float w3 = __expf(a3);
        den = fmaf((w0 + w1) + (w2 + w3), laneden, den);
        float w0o = __shfl_sync(0xffffffffu, w0, hown);
        float w1o = __shfl_sync(0xffffffffu, w1, hown);
        float w2o = __shfl_sync(0xffffffffu, w2, hown);
        float w3o = __shfl_sync(0xffffffffu, w3, hown);
        float2 f0 = __half22float2(q0);
        float2 f1 = __half22float2(q1);
        float2 f2 = __half22float2(q2);
        float2 f3 = __half22float2(q3);
        accx = fmaf(w0o, f0.x, accx);
        accy = fmaf(w0o, f0.y, accy);
        accx = fmaf(w1o, f1.x, accx);
        accy = fmaf(w1o, f1.y, accy);
        accx = fmaf(w2o, f2.x, accx);
        accy = fmaf(w2o, f2.y, accy);
        accx = fmaf(w3o, f3.x, accx);
        accy = fmaf(w3o, f3.y, accy);
    }
    for (; e < end; e++) {
        int s0 = g_col[e];
        float a0 = g_asrc1[s0 * HEADS + h] + adv;
        __half2 q0 = *(const __half2*)&g_h1h[(size_t)s0 * C1 + 2 * lane];
        a0 = a0 > 0.f ? a0 : 0.2f * a0;
        float w0 = __expf(a0);
        den = fmaf(w0, laneden, den);
        float w0o = __shfl_sync(0xffffffffu, w0, hown);
        float2 f0 = __half22float2(q0);
        accx = fmaf(w0o, f0.x, accx);
        accy = fmaf(w0o, f0.y, accy);
    }
    float deno = __shfl_sync(0xffffffffu, den, hown);
    float2 bv = *(const float2*)&bias1[2 * lane];
    float ox = accx / deno + bv.x;
    float oy = accy / deno + bv.y;
    ox = ox > 0.f ? ox : expm1f(ox);          // elu
    oy = oy > 0.f ? oy : expm1f(oy);
    *(float2*)&g_h1act[(size_t)nd * C1 + 2 * lane] = make_float2(ox, oy);
}

// ================= GEMM2: h2 = h1act @ W2, fused scalar logits =================
__global__ __launch_bounds__(256) void gemm2(
    const float* __restrict__ W2, const float* __restrict__ aS,
    const float* __restrict__ aD, int n)
{
    __shared__ float ws[64 * 16];
    int tid = threadIdx.x;
    for (int i = tid; i < 64 * 16; i += 256) ws[i] = W2[i];
    __syncthreads();

    int warp = tid >> 5, lane = tid & 31;
    int row0 = (blockIdx.x * 8 + warp) * 2 + (lane >> 4);
    int c = lane & 15;
    bool ok = row0 < n;
    int row = ok ? row0 : 0;

    float xr[4];
#pragma unroll
    for (int j = 0; j < 4; j++) xr[j] = g_h1act[(size_t)row * C1 + c + 16 * j];

    float acc = 0.f;
#pragma unroll
    for (int k = 0; k < 64; k++) {
        float xk = __shfl_sync(0xffffffffu, xr[k >> 4], (lane & 16) | (k & 15));
        acc = fmaf(xk, ws[k * 16 + c], acc);
    }

    float ts = acc * aS[c];
    float td = acc * aD[c];
#pragma unroll
    for (int off = 8; off >= 1; off >>= 1) {
        ts += __shfl_xor_sync(0xffffffffu, ts, off);
        td += __shfl_xor_sync(0xffffffffu, td, off);
    }
    if (ok) {
        g_h2[(size_t)row * CLS + c] = acc;
        if (c == 0) { g_asrc2[row] = ts; g_adst2[row] = td; }
    }
}

// ================= layer-2 aggregate + bias + log_softmax =================
__global__ __launch_bounds__(256) void agg2(
    const float* __restrict__ bias2, float* __restrict__ out, int n)
{
    int warp = (blockIdx.x * blockDim.x + threadIdx.x) >> 5;
    int lane = threadIdx.x & 31;
    int node0 = warp * 2 + (lane >> 4);
    int c = lane & 15;
    bool ok = node0 < n;
    int nd = ok ? node0 : 0;

    float adv = g_adst2[nd];
    int beg = g_rowptr[nd];
    int end = ok ? g_rowptr[nd + 1] : beg;
    float acc = 0.f, den = 0.f;
    int e = beg;
    for (; e + 2 <= end; e += 2) {
        int s0 = g_col[e], s1 = g_col[e + 1];
        float a0 = g_asrc2[s0] + adv;
        float a1 = g_asrc2[s1] + adv;
        float f0 = g_h2[(size_t)s0 * CLS + c];
        float f1 = g_h2[(size_t)s1 * CLS + c];
        a0 = a0 > 0.f ? a0 : 0.2f * a0;
        a1 = a1 > 0.f ? a1 : 0.2f * a1;
        float w0 = __expf(a0), w1 = __expf(a1);
        den += w0 + w1;
        acc = fmaf(w0, f0, acc);
        acc = fmaf(w1, f1, acc);
    }
    if (e < end) {
        int s0 = g_col[e];
        float a0 = g_asrc2[s0] + adv;
        a0 = a0 > 0.f ? a0 : 0.2f * a0;
        float w0 = __expf(a0);
        den += w0;
        acc = fmaf(w0, g_h2[(size_t)s0 * CLS + c], acc);
    }
    float val = ok ? (acc / den + bias2[c]) : 0.f;
    float m = val;
#pragma unroll
    for (int off = 8; off >= 1; off >>= 1)
        m = fmaxf(m, __shfl_xor_sync(0xffffffffu, m, off));
    float ex = __expf(val - m);
    float s = ex;
#pragma unroll
    for (int off = 8; off >= 1; off >>= 1)
        s += __shfl_xor_sync(0xffffffffu, s, off);
    if (ok) out[(size_t)node0 * CLS + c] = val - m - __logf(s);
}

// ---------------- launch ----------------
extern "C" void kernel_launch(void* const* d_in, const int* in_sizes, int n_in,
                              void* d_out, int out_size) {
    const float* x     = (const float*)d_in[0];
    const void*  ei    = d_in[1];
    const float* W1    = (const float*)d_in[2];
    const float* attS1 = (const float*)d_in[3];
    const float* attD1 = (const float*)d_in[4];
    const float* bias1 = (const float*)d_in[5];
    const float* W2    = (const float*)d_in[6];
    const float* attS2 = (const float*)d_in[7];
    const float* attD2 = (const float*)d_in[8];
    const float* bias2 = (const float*)d_in[9];
    float* out = (float*)d_out;

    int n = in_sizes[0] / F_IN;      // 50000
    int E = in_sizes[1] / 2;         // 1600000

    void *p_deg = nullptr, *p_tmp = nullptr;
    cudaGetSymbolAddress(&p_deg, g_deg);
    cudaGetSymbolAddress(&p_tmp, g_tmp);
    cudaMemsetAsync(p_deg, 0, (size_t)n * sizeof(int));
    cudaMemsetAsync(p_tmp, 0, (size_t)n * sizeof(int));

    int GB = (n + 255) / 256;                 // gemm1 blocks (196)
    int CB = (E + 255) / 256;                 // count blocks (6250)
    int nb = (n + SCAN_B - 1) / SCAN_B;       // scan blocks (196)

    k_gemm1_count<<<GB + CB, 256>>>(x, W1, attS1, attD1, ei, n, E, GB);  // count hidden under gemm1
    k_scan1<<<nb, SCAN_B>>>(n);
    k_scan2<<<1, 256>>>(nb, n);
    k_scan3<<<nb, SCAN_B>>>(n);
    k_scatter<<<(E + n + 255) / 256, 256>>>(ei, E, n);

    agg1 <<<(n + 7) / 8, 256>>>(bias1, n);
    gemm2<<<(n + 15) / 16, 256>>>(W2, attS2, attD2, n);
    agg2 <<<(n + 15) / 16, 256>>>(bias2, out, n);
}

// round 10
// speedup vs baseline: 1.1635x; 1.1066x over previous
#include <cuda_runtime.h>
#include <cuda_fp16.h>
#include <cstdint>

#define MAXN 50000
#define MAXE 1600000
#define F_IN 512
#define C1 64      // heads*hid = 8*8
#define HEADS 8
#define CLS 16
#define SCAN_B 256

// packed fp32x2 FMA (sm_103a)
#define FMA_F32X2(d, a, b, c) \
    asm("fma.rn.f32x2 %0, %1, %2, %3;" : "=l"(d) : "l"(a), "l"(b), "l"(c))
#define PACK_DUP_F32X2(d, f) \
    asm("mov.b64 %0, {%1, %1};" : "=l"(d) : "r"(__float_as_uint(f)))

// ---------------- scratch ----------------
__device__ __align__(16) int   g_deg[MAXN];        // zeroed via cudaMemsetAsync
__device__ __align__(16) int   g_tmp[MAXN];        // zeroed inside k_scan1
__device__ __align__(16) int   g_rowptr[MAXN + 1]; // block-local exclusive prefix
__device__ __align__(16) int   g_bsum[256];
__device__ __align__(16) int   g_boff[256];        // per-block offset (scan3 folded away)
__device__ __align__(16) int   g_col[MAXE + MAXN];
__device__ __align__(16) float g_h1[(size_t)MAXN * C1];
__device__ __align__(16) float g_asrc1[MAXN * HEADS];
__device__ __align__(16) float g_adst1[MAXN * HEADS];
__device__ __align__(16) float g_h1act[(size_t)MAXN * C1];
__device__ __align__(16) float g_h2[(size_t)MAXN * CLS];
__device__ __align__(16) float g_asrc2[MAXN];
__device__ __align__(16) float g_adst2[MAXN];

// global rowptr = block-local prefix + per-block offset
__device__ __forceinline__ int rowp(int i) {
    return g_rowptr[i] + g_boff[i >> 8];
}

// Per-block int64-vs-int32 probe: deterministic for fixed input.
__device__ __forceinline__ bool block_detect_is64(const int* w32, long long e0, int E) {
    int hi = 0;
    long long e = e0 + threadIdx.x;
    if (e < E) hi = w32[2 * e + 1];
    return !__syncthreads_or(hi != 0);
}

__device__ __forceinline__ int load_edge(const void* ei, bool is64, size_t pos) {
    return is64 ? (int)((const long long*)ei)[pos] : ((const int*)ei)[pos];
}

// ================= fused GEMM1 (f32x2 packed) + edge count =================
#define TK 32
__global__ __launch_bounds__(256) void k_gemm1_count(
    const float* __restrict__ x, const float* __restrict__ W,
    const float* __restrict__ attS, const float* __restrict__ attD,
    const void* __restrict__ ei, int n, int E, int GB)
{
    if (blockIdx.x >= GB) {
        long long e0 = (long long)(blockIdx.x - GB) * 256;
        bool is64 = block_detect_is64((const int*)ei, e0, E);
        long long e = e0 + threadIdx.x;
        if (e < E) {
            int d = load_edge(ei, is64, (size_t)E + e);
            if ((unsigned)d < (unsigned)n) atomicAdd(&g_deg[d], 1);
        }
        return;
    }

    __shared__ __align__(16) float xs[TK][256 + 4];
    __shared__ __align__(16) float ws[TK][64 + 4];
    int tid = threadIdx.x;
    int tx = tid & 7;       // col group (== head)
    int ty = tid >> 3;      // row group 0..31
    int r0 = blockIdx.x * 256;

    unsigned long long acc2[8][4];
#pragma unroll
    for (int r = 0; r < 8; r++)
#pragma unroll
        for (int c = 0; c < 4; c++) acc2[r][c] = 0ull;

    for (int kc = 0; kc < F_IN; kc += TK) {
#pragma unroll
        for (int i = 0; i < 8; i++) {
            int idx = tid + 256 * i;
            int row = idx >> 3;
            int k4  = idx & 7;
            float4 v = make_float4(0.f, 0.f, 0.f, 0.f);
            int gr = r0 + row;
            if (gr < n) v = *(const float4*)&x[(size_t)gr * F_IN + kc + k4 * 4];
            xs[k4 * 4 + 0][row] = v.x;
            xs[k4 * 4 + 1][row] = v.y;
            xs[k4 * 4 + 2][row] = v.z;
            xs[k4 * 4 + 3][row] = v.w;
        }
#pragma unroll
        for (int i = 0; i < 2; i++) {
            int idx = tid + 256 * i;
            int k  = idx >> 4;
            int c4 = idx & 15;
            float4 v = *(const float4*)&W[(size_t)(kc + k) * C1 + c4 * 4];
            ws[k][c4 * 4 + 0] = v.x;
            ws[k][c4 * 4 + 1] = v.y;
            ws[k][c4 * 4 + 2] = v.z;
            ws[k][c4 * 4 + 3] = v.w;
        }
        __syncthreads();
#pragma unroll
        for (int k = 0; k < TK; k++) {
            float4 xa = *(const float4*)&xs[k][ty * 8];
            float4 xb = *(const float4*)&xs[k][ty * 8 + 4];
            unsigned long long wv2[4];
            {
                const ulonglong2* wp = (const ulonglong2*)&ws[k][tx * 8];
                ulonglong2 w01 = wp[0];
                ulonglong2 w23 = wp[1];
                wv2[0] = w01.x; wv2[1] = w01.y;
                wv2[2] = w23.x; wv2[3] = w23.y;
            }
            unsigned long long xp[8];
            PACK_DUP_F32X2(xp[0], xa.x); PACK_DUP_F32X2(xp[1], xa.y);
            PACK_DUP_F32X2(xp[2], xa.z); PACK_DUP_F32X2(xp[3], xa.w);
            PACK_DUP_F32X2(xp[4], xb.x); PACK_DUP_F32X2(xp[5], xb.y);
            PACK_DUP_F32X2(xp[6], xb.z); PACK_DUP_F32X2(xp[7], xb.w);
#pragma unroll
            for (int r = 0; r < 8; r++)
#pragma unroll
                for (int c = 0; c < 4; c++)
                    FMA_F32X2(acc2[r][c], xp[r], wv2[c], acc2[r][c]);
        }
        __syncthreads();
    }

    float as[8], ad[8];
#pragma unroll
    for (int c = 0; c < 8; c++) { as[c] = attS[tx * 8 + c]; ad[c] = attD[tx * 8 + c]; }
#pragma unroll
    for (int r = 0; r < 8; r++) {
        int gr = r0 + ty * 8 + r;
        if (gr < n) {
            float a[8];
#pragma unroll
            for (int c = 0; c < 4; c++) {
                uint2 u = *(uint2*)&acc2[r][c];
                a[2 * c]     = __uint_as_float(u.x);
                a[2 * c + 1] = __uint_as_float(u.y);
            }
            float s = 0.f, d = 0.f;
#pragma unroll
            for (int c = 0; c < 8; c++) {
                s = fmaf(a[c], as[c], s);
                d = fmaf(a[c], ad[c], d);
            }
            float4 v0 = make_float4(a[0], a[1], a[2], a[3]);
            float4 v1 = make_float4(a[4], a[5], a[6], a[7]);
            *(float4*)&g_h1[(size_t)gr * C1 + tx * 8]     = v0;
            *(float4*)&g_h1[(size_t)gr * C1 + tx * 8 + 4] = v1;
            g_asrc1[gr * HEADS + tx] = s;
            g_adst1[gr * HEADS + tx] = d;
        }
    }
}

// ================= 2-stage block scan (offsets applied on the fly) =================
__device__ __forceinline__ int warp_incl_scan(int x) {
#pragma unroll
    for (int o = 1; o < 32; o <<= 1) {
        int t = __shfl_up_sync(0xffffffffu, x, o);
        if ((threadIdx.x & 31) >= o) x += t;
    }
    return x;
}

__global__ void k_scan1(int n) {
    __shared__ int wsum[8];
    int i = blockIdx.x * SCAN_B + threadIdx.x;
    int lane = threadIdx.x & 31, wid = threadIdx.x >> 5;
    if (i < n) g_tmp[i] = 0;                // replaces the g_tmp memset
    int v = (i < n) ? g_deg[i] + 1 : 0;     // +1 = self-loop
    int x = warp_incl_scan(v);
    if (lane == 31) wsum[wid] = x;
    __syncthreads();
    if (wid == 0) {
        int y = (lane < 8) ? wsum[lane] : 0;
#pragma unroll
        for (int o = 1; o < 8; o <<= 1) {
            int t = __shfl_up_sync(0xffffffffu, y, o);
            if (lane >= o) y += t;
        }
        if (lane < 8) wsum[lane] = y;
    }
    __syncthreads();
    int excl = x - v + (wid > 0 ? wsum[wid - 1] : 0);
    if (i <= n) g_rowptr[i] = excl;         // i==n gets block-local prefix (v=0 there)
    if (threadIdx.x == 0) g_bsum[blockIdx.x] = wsum[7];
}

__global__ void k_scan2(int nb) {           // nb <= 256; produces g_boff only
    __shared__ int wsum[8];
    int t = threadIdx.x;
    int lane = t & 31, wid = t >> 5;
    int v = (t < nb) ? g_bsum[t] : 0;
    int x = warp_incl_scan(v);
    if (lane == 31) wsum[wid] = x;
    __syncthreads();
    if (wid == 0) {
        int y = (lane < 8) ? wsum[lane] : 0;
#pragma unroll
        for (int o = 1; o < 8; o <<= 1) {
            int tt = __shfl_up_sync(0xffffffffu, y, o);
            if (lane >= o) y += tt;
        }
        if (lane < 8) wsum[lane] = y;
    }
    __syncthreads();
    int excl = x - v + (wid > 0 ? wsum[wid - 1] : 0);
    if (t < nb) g_boff[t] = excl;
}

// ================= scatter (edges then self-loops) =================
__global__ void k_scatter(const void* __restrict__ ei, int E, int n) {
    long long e0 = (long long)blockIdx.x * 256;
    bool is64 = block_detect_is64((const int*)ei, e0, E);
    long long i = e0 + threadIdx.x;
    int s, d;
    if (i < E) {
        d = load_edge(ei, is64, (size_t)E + i);
        if ((unsigned)d >= (unsigned)n) return;       // must match k_count guard
        s = load_edge(ei, is64, (size_t)i);
        if ((unsigned)s >= (unsigned)n) s = 0;
    } else if (i < E + n) {
        s = d = (int)(i - E);
    } else return;
    int pos = rowp(d) + atomicAdd(&g_tmp[d], 1);
    g_col[pos] = s;
}

// ================= layer-1 edge softmax + aggregate + bias + elu =================
// one warp per dst node; lane owns channels 2l, 2l+1 (head hown = l>>2); 4-way unroll.
__global__ __launch_bounds__(256) void agg1(const float* __restrict__ bias1, int n) {
    int warp = (blockIdx.x * blockDim.x + threadIdx.x) >> 5;
    int lane = threadIdx.x & 31;
    if (warp >= n) return;
    int nd = warp;
    int h    = lane & 7;
    int hown = lane >> 2;
    float laneden = (lane < 8) ? 1.f : 0.f;

    float adv = g_adst1[nd * HEADS + h];
    int beg = rowp(nd), end = rowp(nd + 1);
    float accx = 0.f, accy = 0.f, den = 0.f;

    int e = beg;
    for (; e + 4 <= end; e += 4) {
        int s0 = g_col[e];
        int s1 = g_col[e + 1];
        int s2 = g_col[e + 2];
        int s3 = g_col[e + 3];
        float a0 = g_asrc1[s0 * HEADS + h] + adv;
        float a1 = g_asrc1[s1 * HEADS + h] + adv;
        float a2 = g_asrc1[s2 * HEADS + h] + adv;
        float a3 = g_asrc1[s3 * HEADS + h] + adv;
        float2 f0 = *(const float2*)&g_h1[(size_t)s0 * C1 + 2 * lane];
        float2 f1 = *(const float2*)&g_h1[(size_t)s1 * C1 + 2 * lane];
        float2 f2 = *(const float2*)&g_h1[(size_t)s2 * C1 + 2 * lane];
        float2 f3 = *(const float2*)&g_h1[(size_t)s3 * C1 + 2 * lane];
        a0 = a0 > 0.f ? a0 : 0.2f * a0;
        a1 = a1 > 0.f ? a1 : 0.2f * a1;
        a2 = a2 > 0.f ? a2 : 0.2f * a2;
        a3 = a3 > 0.f ? a3 : 0.2f * a3;
        float w0 = __expf(a0);
        float w1 = __expf(a1);
        float w2 = __expf(a2);
        float w3 = __expf(a3);
        den = fmaf((w0 + w1) + (w2 + w3), laneden, den);
        float w0o = __shfl_sync(0xffffffffu, w0, hown);
        float w1o = __shfl_sync(0xffffffffu, w1, hown);
        float w2o = __shfl_sync(0xffffffffu, w2, hown);
        float w3o = __shfl_sync(0xffffffffu, w3, hown);
        accx = fmaf(w0o, f0.x, accx);
        accy = fmaf(w0o, f0.y, accy);
        accx = fmaf(w1o, f1.x, accx);
        accy = fmaf(w1o, f1.y, accy);
        accx = fmaf(w2o, f2.x, accx);
        accy = fmaf(w2o, f2.y, accy);
        accx = fmaf(w3o, f3.x, accx);
        accy = fmaf(w3o, f3.y, accy);
    }
    for (; e < end; e++) {
        int s0 = g_col[e];
        float a0 = g_asrc1[s0 * HEADS + h] + adv;
        float2 f0 = *(const float2*)&g_h1[(size_t)s0 * C1 + 2 * lane];
        a0 = a0 > 0.f ? a0 : 0.2f * a0;
        float w0 = __expf(a0);
        den = fmaf(w0, laneden, den);
        float w0o = __shfl_sync(0xffffffffu, w0, hown);
        accx = fmaf(w0o, f0.x, accx);
        accy = fmaf(w0o, f0.y, accy);
    }
    float deno = __shfl_sync(0xffffffffu, den, hown);
    float2 bv = *(const float2*)&bias1[2 * lane];
    float ox = accx / deno + bv.x;
    float oy = accy / deno + bv.y;
    ox = ox > 0.f ? ox : expm1f(ox);          // elu
    oy = oy > 0.f ? oy : expm1f(oy);
    *(float2*)&g_h1act[(size_t)nd * C1 + 2 * lane] = make_float2(ox, oy);
}

// ================= GEMM2: h2 = h1act @ W2, fused scalar logits =================
__global__ __launch_bounds__(256) void gemm2(
    const float* __restrict__ W2, const float* __restrict__ aS,
    const float* __restrict__ aD, int n)
{
    __shared__ float ws[64 * 16];
    int tid = threadIdx.x;
    for (int i = tid; i < 64 * 16; i += 256) ws[i] = W2[i];
    __syncthreads();

    int warp = tid >> 5, lane = tid & 31;
    int row0 = (blockIdx.x * 8 + warp) * 2 + (lane >> 4);
    int c = lane & 15;
    bool ok = row0 < n;
    int row = ok ? row0 : 0;

    float xr[4];
#pragma unroll
    for (int j = 0; j < 4; j++) xr[j] = g_h1act[(size_t)row * C1 + c + 16 * j];

    float acc = 0.f;
#pragma unroll
    for (int k = 0; k < 64; k++) {
        float xk = __shfl_sync(0xffffffffu, xr[k >> 4], (lane & 16) | (k & 15));
        acc = fmaf(xk, ws[k * 16 + c], acc);
    }

    float ts = acc * aS[c];
    float td = acc * aD[c];
#pragma unroll
    for (int off = 8; off >= 1; off >>= 1) {
        ts += __shfl_xor_sync(0xffffffffu, ts, off);
        td += __shfl_xor_sync(0xffffffffu, td, off);
    }
    if (ok) {
        g_h2[(size_t)row * CLS + c] = acc;
        if (c == 0) { g_asrc2[row] = ts; g_adst2[row] = td; }
    }
}

// ================= layer-2 aggregate + bias + log_softmax =================
__global__ __launch_bounds__(256) void agg2(
    const float* __restrict__ bias2, float* __restrict__ out, int n)
{
    int warp = (blockIdx.x * blockDim.x + threadIdx.x) >> 5;
    int lane = threadIdx.x & 31;
    int node0 = warp * 2 + (lane >> 4);
    int c = lane & 15;
    bool ok = node0 < n;
    int nd = ok ? node0 : 0;

    float adv = g_adst2[nd];
    int beg = rowp(nd);
    int end = ok ? rowp(nd + 1) : beg;
    float acc = 0.f, den = 0.f;
    int e = beg;
    for (; e + 2 <= end; e += 2) {
        int s0 = g_col[e], s1 = g_col[e + 1];
        float a0 = g_asrc2[s0] + adv;
        float a1 = g_asrc2[s1] + adv;
        float f0 = g_h2[(size_t)s0 * CLS + c];
        float f1 = g_h2[(size_t)s1 * CLS + c];
        a0 = a0 > 0.f ? a0 : 0.2f * a0;
        a1 = a1 > 0.f ? a1 : 0.2f * a1;
        float w0 = __expf(a0), w1 = __expf(a1);
        den += w0 + w1;
        acc = fmaf(w0, f0, acc);
        acc = fmaf(w1, f1, acc);
    }
    if (e < end) {
        int s0 = g_col[e];
        float a0 = g_asrc2[s0] + adv;
        a0 = a0 > 0.f ? a0 : 0.2f * a0;
        float w0 = __expf(a0);
        den += w0;
        acc = fmaf(w0, g_h2[(size_t)s0 * CLS + c], acc);
    }
    float val = ok ? (acc / den + bias2[c]) : 0.f;
    float m = val;
#pragma unroll
    for (int off = 8; off >= 1; off >>= 1)
        m = fmaxf(m, __shfl_xor_sync(0xffffffffu, m, off));
    float ex = __expf(val - m);
    float s = ex;
#pragma unroll
    for (int off = 8; off >= 1; off >>= 1)
        s += __shfl_xor_sync(0xffffffffu, s, off);
    if (ok) out[(size_t)node0 * CLS + c] = val - m - __logf(s);
}

// ---------------- launch ----------------
extern "C" void kernel_launch(void* const* d_in, const int* in_sizes, int n_in,
                              void* d_out, int out_size) {
    const float* x     = (const float*)d_in[0];
    const void*  ei    = d_in[1];
    const float* W1    = (const float*)d_in[2];
    const float* attS1 = (const float*)d_in[3];
    const float* attD1 = (const float*)d_in[4];
    const float* bias1 = (const float*)d_in[5];
    const float* W2    = (const float*)d_in[6];
    const float* attS2 = (const float*)d_in[7];
    const float* attD2 = (const float*)d_in[8];
    const float* bias2 = (const float*)d_in[9];
    float* out = (float*)d_out;

    int n = in_sizes[0] / F_IN;      // 50000
    int E = in_sizes[1] / 2;         // 1600000

    void* p_deg = nullptr;
    cudaGetSymbolAddress(&p_deg, g_deg);
    cudaMemsetAsync(p_deg, 0, (size_t)n * sizeof(int));   // launch 1

    int GB = (n + 255) / 256;                 // gemm1 blocks (196)
    int CB = (E + 255) / 256;                 // count blocks (6250)
    int nb = (n + SCAN_B - 1) / SCAN_B;       // scan blocks (196)

    k_gemm1_count<<<GB + CB, 256>>>(x, W1, attS1, attD1, ei, n, E, GB); // 2
    k_scan1<<<nb, SCAN_B>>>(n);                                         // 3 (also zeroes g_tmp)
    k_scan2<<<1, 256>>>(nb);                                            // 4
    k_scatter<<<(E + n + 255) / 256, 256>>>(ei, E, n);                  // 5
    agg1 <<<(n + 7) / 8, 256>>>(bias1, n);                              // 6  <- ncu -s 5 lands here
    gemm2<<<(n + 15) / 16, 256>>>(W2, attS2, attD2, n);
    agg2 <<<(n + 15) / 16, 256>>>(bias2, out, n);
}